// round 1
// baseline (speedup 1.0000x reference)
#include <cuda_runtime.h>
#include <math.h>

// Problem constants
#define BB   256   // batch
#define TT   512   // timesteps
#define HH   256   // hidden
#define LL   4     // layers

#define NBLK 128   // persistent blocks (<=148 SMs, all co-resident)
#define NTHR 256
#define JT   16    // hidden units per block
#define BT   32    // batch rows per block
#define NBT  8     // batch tiles (BB/BT)
#define SROW 34    // padded smem row stride (32 batch + 2 pad, keeps float2 aligned, conflict-free)
#define NBAR (LL * TT)

// Scratch (allocation-free rule: __device__ globals)
__device__ float g_bufA[(size_t)TT * BB * HH];
__device__ float g_bufB[(size_t)TT * BB * HH];
__device__ unsigned g_bar[NBAR];   // zero-initialized at load; reset at kernel end

struct Params {
    const float* x;
    const float* Wih[LL];
    const float* Whh[LL];
    const float* bih[LL];
    const float* bhh[LL];
    const float* fcW;
    const float* fcb;
    float* out;
};

__device__ __forceinline__ float sigf(float v) {
    return 1.0f / (1.0f + expf(-v));
}

// DIY grid barrier: release (fence) -> atomic arrive -> spin -> acquire (fence)
__device__ __forceinline__ void grid_bar(int slot) {
    __syncthreads();
    if (threadIdx.x == 0) {
        __threadfence();
        atomicAdd(&g_bar[slot], 1u);
        while (((volatile unsigned*)g_bar)[slot] < (unsigned)NBLK) { }
        __threadfence();
    }
    __syncthreads();
}

// Load [BT x HH] contiguous global tile into smem transposed [k][b] with padded rows.
// Consecutive threads read consecutive global floats (coalesced); STS is 2-way at worst.
__device__ __forceinline__ void load_tile(const float* __restrict__ g, float* __restrict__ s) {
    #pragma unroll 4
    for (int i = threadIdx.x; i < BT * HH; i += NTHR) {
        int bb = i >> 8;          // / HH
        int jj = i & (HH - 1);
        s[jj * SROW + bb] = g[i];
    }
}

// acc[gate][b] += sum_k W[gate*H + j][k] * s[k][b_off + {0,1}]
__device__ __forceinline__ void gemm_tile(const float* __restrict__ W, int j,
                                          const float* __restrict__ s, int b_off,
                                          float a[4][2]) {
    const float* r0 = W + (size_t)(0 * HH + j) * HH;
    const float* r1 = W + (size_t)(1 * HH + j) * HH;
    const float* r2 = W + (size_t)(2 * HH + j) * HH;
    const float* r3 = W + (size_t)(3 * HH + j) * HH;
    #pragma unroll 2
    for (int k4 = 0; k4 < HH; k4 += 4) {
        float4 w0 = *(const float4*)(r0 + k4);
        float4 w1 = *(const float4*)(r1 + k4);
        float4 w2 = *(const float4*)(r2 + k4);
        float4 w3 = *(const float4*)(r3 + k4);
        #pragma unroll
        for (int q = 0; q < 4; ++q) {
            float2 hb = *(const float2*)(s + (k4 + q) * SROW + b_off);
            float w0q = ((const float*)&w0)[q];
            float w1q = ((const float*)&w1)[q];
            float w2q = ((const float*)&w2)[q];
            float w3q = ((const float*)&w3)[q];
            a[0][0] = fmaf(w0q, hb.x, a[0][0]); a[0][1] = fmaf(w0q, hb.y, a[0][1]);
            a[1][0] = fmaf(w1q, hb.x, a[1][0]); a[1][1] = fmaf(w1q, hb.y, a[1][1]);
            a[2][0] = fmaf(w2q, hb.x, a[2][0]); a[2][1] = fmaf(w2q, hb.y, a[2][1]);
            a[3][0] = fmaf(w3q, hb.x, a[3][0]); a[3][1] = fmaf(w3q, hb.y, a[3][1]);
        }
    }
}

__global__ void __launch_bounds__(NTHR, 1) lstm_persistent(Params p) {
    extern __shared__ float s[];    // [HH][SROW]
    const int tid   = threadIdx.x;
    const int bid   = blockIdx.x;
    const int jt    = bid >> 3;          // 0..15 hidden tile
    const int bt    = bid & 7;           // 0..7  batch tile
    const int j_idx = tid >> 4;          // 0..15
    const int b_idx = tid & 15;          // 0..15
    const int j     = jt * JT + j_idx;   // global hidden unit owned by this thread
    const int b0    = bt * BT + 2 * b_idx;
    const int b_off = 2 * b_idx;

    int slot = 0;
    float* bufA = g_bufA;
    float* bufB = g_bufB;

    for (int l = 0; l < LL; ++l) {
        const float* Wih = p.Wih[l];
        const float* Whh = p.Whh[l];
        float bias[4];
        #pragma unroll
        for (int gi = 0; gi < 4; ++gi)
            bias[gi] = p.bih[l][gi * HH + j] + p.bhh[l][gi * HH + j];
        float wx[4] = {0.f, 0.f, 0.f, 0.f};
        if (l == 0) {
            #pragma unroll
            for (int gi = 0; gi < 4; ++gi) wx[gi] = Wih[gi * HH + j];  // W_ih0 is [4H,1]
        }
        const float* inb = (l & 1) ? bufA : bufB;   // l=1 reads A, l=2 reads B, l=3 reads A
        float*       outb = (l & 1) ? bufB : bufA;  // l=0 writes A, l=1 B, l=2 A, l=3 B

        float c0 = 0.f, c1 = 0.f;

        for (int t = 0; t < TT; ++t) {
            float a[4][2];
            #pragma unroll
            for (int gi = 0; gi < 4; ++gi) { a[gi][0] = bias[gi]; a[gi][1] = bias[gi]; }

            if (l == 0) {
                float xv0 = p.x[(size_t)b0 * TT + t];
                float xv1 = p.x[(size_t)(b0 + 1) * TT + t];
                #pragma unroll
                for (int gi = 0; gi < 4; ++gi) {
                    a[gi][0] = fmaf(wx[gi], xv0, a[gi][0]);
                    a[gi][1] = fmaf(wx[gi], xv1, a[gi][1]);
                }
            } else {
                load_tile(inb + ((size_t)t * BB + bt * BT) * HH, s);
                __syncthreads();
                gemm_tile(Wih, j, s, b_off, a);
                __syncthreads();
            }

            if (t > 0) {
                load_tile(outb + ((size_t)(t - 1) * BB + bt * BT) * HH, s);
                __syncthreads();
                gemm_tile(Whh, j, s, b_off, a);
            }

            // elementwise LSTM cell (PyTorch gate order i,f,g,o)
            float i0 = sigf(a[0][0]), f0 = sigf(a[1][0]);
            float g0 = tanhf(a[2][0]), o0 = sigf(a[3][0]);
            c0 = f0 * c0 + i0 * g0;
            float h0 = o0 * tanhf(c0);

            float i1 = sigf(a[0][1]), f1 = sigf(a[1][1]);
            float g1 = tanhf(a[2][1]), o1 = sigf(a[3][1]);
            c1 = f1 * c1 + i1 * g1;
            float h1 = o1 * tanhf(c1);

            size_t ob = (size_t)t * BB * HH;
            outb[ob + (size_t)b0 * HH + j]       = h0;
            outb[ob + (size_t)(b0 + 1) * HH + j] = h1;

            grid_bar(slot++);
        }
    }

    // Final FC on last timestep of layer 3 (lives in bufB) + barrier reset for replays
    if (bid == 0) {
        const float* hlast = g_bufB + (size_t)(TT - 1) * BB * HH;
        for (int b = tid; b < BB; b += NTHR) {
            float acc = p.fcb[0];
            const float* hr = hlast + (size_t)b * HH;
            #pragma unroll 4
            for (int k = 0; k < HH; ++k) acc = fmaf(hr[k], p.fcW[k], acc);
            p.out[b] = acc;
        }
        for (int i = tid; i < NBAR; i += NTHR) g_bar[i] = 0;
    }
}

extern "C" void kernel_launch(void* const* d_in, const int* in_sizes, int n_in,
                              void* d_out, int out_size) {
    (void)in_sizes; (void)n_in; (void)out_size;
    Params p;
    p.x = (const float*)d_in[0];
    for (int l = 0; l < LL; ++l) {
        p.Wih[l] = (const float*)d_in[1 + 4 * l];
        p.Whh[l] = (const float*)d_in[2 + 4 * l];
        p.bih[l] = (const float*)d_in[3 + 4 * l];
        p.bhh[l] = (const float*)d_in[4 + 4 * l];
    }
    p.fcW = (const float*)d_in[17];
    p.fcb = (const float*)d_in[18];
    p.out = (float*)d_out;

    lstm_persistent<<<NBLK, NTHR, SROW * HH * sizeof(float)>>>(p);
}

// round 2
// speedup vs baseline: 2.8063x; 2.8063x over previous
#include <cuda_runtime.h>
#include <cuda_bf16.h>
#include <math.h>

typedef unsigned int u32;

#define BB   256
#define TT   512
#define HH   256
#define LL   4

#define NBLK 128
#define NTHR 256
#define NBAR (LL * TT)

// smem strides (in 32-bit words)
#define AS   132   // A (weights) row stride: 128 k-pair words + 4 pad (conflict-free frag loads)
#define BS   40    // B (h) row stride: 32 batch + 8 pad (conflict-free frag loads)
#define GS   33    // gate smem row stride

// smem layout sizes (words)
#define SZ_A (64 * AS)        // 8448
#define SZ_B (128 * BS)       // 5120
#define SZ_G (64 * GS)        // 2112
#define SMEM_WORDS (2 * SZ_A + 2 * SZ_B + SZ_G + 64 + 64)
#define SMEM_BYTES (SMEM_WORDS * 4)

// ---------------- device scratch (allocation-free rule) ----------------
// h sequences, packed bf16 pairs: word (t, k2, b) = {h[2k2], h[2k2+1]} for batch b
__device__ __align__(128) u32 g_hAhi[TT * 128 * BB];
__device__ __align__(128) u32 g_hAlo[TT * 128 * BB];
__device__ __align__(128) u32 g_hBhi[TT * 128 * BB];
__device__ __align__(128) u32 g_hBlo[TT * 128 * BB];
// per-block input-projection gates, fp32: [block][t][64 m][32 n]
__device__ __align__(128) float g_gih[(size_t)NBLK * TT * 64 * 32];
__device__ unsigned g_bar[NBAR];

struct Params {
    const float* x;
    const float* Wih[LL];
    const float* Whh[LL];
    const float* bih[LL];
    const float* bhh[LL];
    const float* fcW;
    const float* fcb;
    float* out;
};

// ---------------- helpers ----------------
__device__ __forceinline__ float sigf(float v) {
    return __fdividef(1.0f, 1.0f + __expf(-v));
}
__device__ __forceinline__ float tanhfast(float v) {
    return 1.0f - __fdividef(2.0f, __expf(2.0f * v) + 1.0f);
}

__device__ __forceinline__ void split_pack(float x, float y, u32& hi, u32& lo) {
    __nv_bfloat162 h2, l2;
    h2.x = __float2bfloat16_rn(x);
    h2.y = __float2bfloat16_rn(y);
    l2.x = __float2bfloat16_rn(x - __bfloat162float(h2.x));
    l2.y = __float2bfloat16_rn(y - __bfloat162float(h2.y));
    hi = *reinterpret_cast<u32*>(&h2);
    lo = *reinterpret_cast<u32*>(&l2);
}

__device__ __forceinline__ void mma16816(float c[4], u32 a0, u32 a1, u32 a2, u32 a3,
                                         u32 b0, u32 b1) {
    asm("mma.sync.aligned.m16n8k16.row.col.f32.bf16.bf16.f32 "
        "{%0,%1,%2,%3}, {%4,%5,%6,%7}, {%8,%9}, {%0,%1,%2,%3};"
        : "+f"(c[0]), "+f"(c[1]), "+f"(c[2]), "+f"(c[3])
        : "r"(a0), "r"(a1), "r"(a2), "r"(a3), "r"(b0), "r"(b1));
}

// full K=256 warp-tile MMA: accum c[2][4] over sA(hi/lo) x sB(hi/lo), 3 split passes
__device__ __forceinline__ void mma_tile(const u32* __restrict__ sAhi, const u32* __restrict__ sAlo,
                                         const u32* __restrict__ sBhi, const u32* __restrict__ sBlo,
                                         int mb, int wn, int lr, int lc, float c[2][4]) {
    #pragma unroll 4
    for (int kk = 0; kk < 16; ++kk) {
        const int ab = kk * 8 + lc;
        const u32 ah0 = sAhi[(mb + lr) * AS + ab];
        const u32 ah1 = sAhi[(mb + 8 + lr) * AS + ab];
        const u32 ah2 = sAhi[(mb + lr) * AS + ab + 4];
        const u32 ah3 = sAhi[(mb + 8 + lr) * AS + ab + 4];
        const u32 al0 = sAlo[(mb + lr) * AS + ab];
        const u32 al1 = sAlo[(mb + 8 + lr) * AS + ab];
        const u32 al2 = sAlo[(mb + lr) * AS + ab + 4];
        const u32 al3 = sAlo[(mb + 8 + lr) * AS + ab + 4];
        #pragma unroll
        for (int nb = 0; nb < 2; ++nb) {
            const int col = wn * 16 + nb * 8 + lr;
            const u32 bh0 = sBhi[(kk * 8 + lc) * BS + col];
            const u32 bh1 = sBhi[(kk * 8 + 4 + lc) * BS + col];
            const u32 bl0 = sBlo[(kk * 8 + lc) * BS + col];
            const u32 bl1 = sBlo[(kk * 8 + 4 + lc) * BS + col];
            mma16816(c[nb], ah0, ah1, ah2, ah3, bh0, bh1);   // hi*hi
            mma16816(c[nb], ah0, ah1, ah2, ah3, bl0, bl1);   // hi*lo
            mma16816(c[nb], al0, al1, al2, al3, bh0, bh1);   // lo*hi
        }
    }
}

__device__ __forceinline__ void grid_bar(int slot) {
    __syncthreads();
    if (threadIdx.x == 0) {
        __threadfence();
        atomicAdd(&g_bar[slot], 1u);
        while (((volatile unsigned*)g_bar)[slot] < (unsigned)NBLK) { }
        __threadfence();
    }
    __syncthreads();
}

// convert W rows for this block into smem as bf16 hi/lo k-pairs. caller syncs.
__device__ __forceinline__ void load_W(const float* __restrict__ W, int j0,
                                       u32* __restrict__ sAhi, u32* __restrict__ sAlo) {
    for (int i = threadIdx.x; i < 64 * 128; i += NTHR) {
        const int m = i >> 7;
        const int k2 = i & 127;
        const int row = (m >> 4) * HH + j0 + (m & 15);
        const float2 w = *(const float2*)(W + (size_t)row * HH + 2 * k2);
        split_pack(w.x, w.y, sAhi[m * AS + k2], sAlo[m * AS + k2]);
    }
}

// load h tile (k2 0..127, batch b0..b0+31) from global packed buffers into smem. caller syncs.
__device__ __forceinline__ void load_B(const u32* __restrict__ ghi, const u32* __restrict__ glo,
                                       int t, int b0,
                                       u32* __restrict__ sBhi, u32* __restrict__ sBlo) {
    const u32* bh = ghi + (size_t)t * 128 * BB + b0;
    const u32* bl = glo + (size_t)t * 128 * BB + b0;
    for (int i = threadIdx.x; i < 128 * 32; i += NTHR) {
        const int k2 = i >> 5;
        const int bb = i & 31;
        sBhi[k2 * BS + bb] = bh[k2 * BB + bb];
        sBlo[k2 * BS + bb] = bl[k2 * BB + bb];
    }
}

// ---------------- kernel ----------------
__global__ void __launch_bounds__(NTHR, 1) lstm_mma(Params p) {
    extern __shared__ u32 smem[];
    u32*   sAhi = smem;
    u32*   sAlo = sAhi + SZ_A;
    u32*   sBhi = sAlo + SZ_A;
    u32*   sBlo = sBhi + SZ_B;
    float* gsm  = (float*)(sBlo + SZ_B);
    float* bs   = gsm + SZ_G;
    float* wxs  = bs + 64;

    const int tid = threadIdx.x;
    const int bid = blockIdx.x;
    const int jt  = bid >> 3;          // 0..15
    const int bt  = bid & 7;           // 0..7
    const int j0  = jt * 16;
    const int b0  = bt * 32;

    const int wid = tid >> 5;
    const int lane = tid & 31;
    const int lr = lane >> 2;          // 0..7
    const int lc = lane & 3;           // 0..3
    const int mb = (wid >> 1) * 16;    // warp m-base
    const int wn = wid & 1;            // warp n-half

    float* gG0 = g_gih + (size_t)bid * TT * 2048;

    int slot = 0;

    for (int l = 0; l < LL; ++l) {
        // bias (+ rank-1 input weight for layer 0)
        if (tid < 64) {
            const int row = (tid >> 4) * HH + j0 + (tid & 15);
            bs[tid] = p.bih[l][row] + p.bhh[l][row];
            if (l == 0) wxs[tid] = p.Wih[0][row];   // W_ih0 is [4H,1]
        }
        __syncthreads();

        const u32* inhi = (l & 1) ? g_hAhi : g_hBhi;
        const u32* inlo = (l & 1) ? g_hAlo : g_hBlo;
        u32* outhi = (l & 1) ? g_hBhi : g_hAhi;
        u32* outlo = (l & 1) ? g_hBlo : g_hAlo;

        // ---- phase 1: input projections for all t (no cross-block deps) ----
        if (l == 0) {
            for (int idx = tid; idx < 2048; idx += NTHR) {
                const int m = idx >> 5;
                const int n = idx & 31;
                const float wm = wxs[m];
                const float bm = bs[m];
                const float* xr = p.x + (size_t)(b0 + n) * TT;
                float* gw = gG0 + idx;
                for (int t = 0; t < TT; ++t)
                    gw[(size_t)t * 2048] = fmaf(wm, xr[t], bm);
            }
        } else {
            load_W(p.Wih[l], j0, sAhi, sAlo);
            __syncthreads();
            for (int t = 0; t < TT; ++t) {
                __syncthreads();
                load_B(inhi, inlo, t, b0, sBhi, sBlo);
                __syncthreads();
                float c[2][4];
                #pragma unroll
                for (int nb = 0; nb < 2; ++nb) {
                    c[nb][0] = c[nb][1] = bs[mb + lr];
                    c[nb][2] = c[nb][3] = bs[mb + 8 + lr];
                }
                mma_tile(sAhi, sAlo, sBhi, sBlo, mb, wn, lr, lc, c);
                float* gw = gG0 + (size_t)t * 2048;
                #pragma unroll
                for (int nb = 0; nb < 2; ++nb) {
                    const int col = wn * 16 + nb * 8 + 2 * lc;
                    *(float2*)(gw + (mb + lr) * 32 + col)     = make_float2(c[nb][0], c[nb][1]);
                    *(float2*)(gw + (mb + 8 + lr) * 32 + col) = make_float2(c[nb][2], c[nb][3]);
                }
            }
        }
        __syncthreads();

        // ---- phase 2: sequential recurrence ----
        load_W(p.Whh[l], j0, sAhi, sAlo);
        __syncthreads();

        // per-thread cell state: thread owns hidden pair (2jp, 2jp+1) x batch bb
        const int jp = tid >> 5;       // 0..7
        const int bb = tid & 31;       // 0..31
        float cc0 = 0.f, cc1 = 0.f;

        for (int t = 0; t < TT; ++t) {
            if (t > 0) {
                __syncthreads();
                load_B(outhi, outlo, t - 1, b0, sBhi, sBlo);
                __syncthreads();
            }
            float c[2][4];
            {   // init accumulators from precomputed input gates
                const float* gw = gG0 + (size_t)t * 2048;
                #pragma unroll
                for (int nb = 0; nb < 2; ++nb) {
                    const int col = wn * 16 + nb * 8 + 2 * lc;
                    const float2 c01 = *(const float2*)(gw + (mb + lr) * 32 + col);
                    const float2 c23 = *(const float2*)(gw + (mb + 8 + lr) * 32 + col);
                    c[nb][0] = c01.x; c[nb][1] = c01.y;
                    c[nb][2] = c23.x; c[nb][3] = c23.y;
                }
            }
            if (t > 0)
                mma_tile(sAhi, sAlo, sBhi, sBlo, mb, wn, lr, lc, c);

            // dump gates to smem
            #pragma unroll
            for (int nb = 0; nb < 2; ++nb) {
                const int col = wn * 16 + nb * 8 + 2 * lc;
                gsm[(mb + lr) * GS + col]         = c[nb][0];
                gsm[(mb + lr) * GS + col + 1]     = c[nb][1];
                gsm[(mb + 8 + lr) * GS + col]     = c[nb][2];
                gsm[(mb + 8 + lr) * GS + col + 1] = c[nb][3];
            }
            __syncthreads();

            // elementwise LSTM cell for the owned pair
            {
                const int jl0 = 2 * jp, jl1 = 2 * jp + 1;
                const float ig0 = gsm[(jl0) * GS + bb];
                const float fg0 = gsm[(16 + jl0) * GS + bb];
                const float gg0 = gsm[(32 + jl0) * GS + bb];
                const float og0 = gsm[(48 + jl0) * GS + bb];
                const float ig1 = gsm[(jl1) * GS + bb];
                const float fg1 = gsm[(16 + jl1) * GS + bb];
                const float gg1 = gsm[(32 + jl1) * GS + bb];
                const float og1 = gsm[(48 + jl1) * GS + bb];

                cc0 = sigf(fg0) * cc0 + sigf(ig0) * tanhfast(gg0);
                cc1 = sigf(fg1) * cc1 + sigf(ig1) * tanhfast(gg1);
                const float h0 = sigf(og0) * tanhfast(cc0);
                const float h1 = sigf(og1) * tanhfast(cc1);

                u32 hiw, low;
                split_pack(h0, h1, hiw, low);
                const size_t widx = ((size_t)t * 128 + (j0 >> 1) + jp) * BB + b0 + bb;
                outhi[widx] = hiw;
                outlo[widx] = low;
            }
            grid_bar(slot++);
        }
        // reset cell state handled by re-init at next layer
    }

    // ---- final FC on h(T-1) of layer 3 (buffer B) + barrier reset ----
    if (bid == 0) {
        const int b = tid;  // 256 threads, 256 batch rows
        float acc = p.fcb[0];
        const u32* bh = g_hBhi + ((size_t)(TT - 1) * 128) * BB + b;
        const u32* bl = g_hBlo + ((size_t)(TT - 1) * 128) * BB + b;
        for (int k2 = 0; k2 < 128; ++k2) {
            const u32 hw = bh[k2 * BB];
            const u32 lw = bl[k2 * BB];
            const __nv_bfloat162 h2 = *reinterpret_cast<const __nv_bfloat162*>(&hw);
            const __nv_bfloat162 l2 = *reinterpret_cast<const __nv_bfloat162*>(&lw);
            const float h0 = __bfloat162float(h2.x) + __bfloat162float(l2.x);
            const float h1 = __bfloat162float(h2.y) + __bfloat162float(l2.y);
            const float2 w = *(const float2*)(p.fcW + 2 * k2);
            acc = fmaf(w.x, h0, fmaf(w.y, h1, acc));
        }
        p.out[b] = acc;
        for (int i = tid; i < NBAR; i += NTHR) g_bar[i] = 0;
    }
}

extern "C" void kernel_launch(void* const* d_in, const int* in_sizes, int n_in,
                              void* d_out, int out_size) {
    (void)in_sizes; (void)n_in; (void)out_size;
    Params p;
    p.x = (const float*)d_in[0];
    for (int l = 0; l < LL; ++l) {
        p.Wih[l] = (const float*)d_in[1 + 4 * l];
        p.Whh[l] = (const float*)d_in[2 + 4 * l];
        p.bih[l] = (const float*)d_in[3 + 4 * l];
        p.bhh[l] = (const float*)d_in[4 + 4 * l];
    }
    p.fcW = (const float*)d_in[17];
    p.fcb = (const float*)d_in[18];
    p.out = (float*)d_out;

    cudaFuncSetAttribute(lstm_mma, cudaFuncAttributeMaxDynamicSharedMemorySize, SMEM_BYTES);
    lstm_mma<<<NBLK, NTHR, SMEM_BYTES>>>(p);
}